// round 1
// baseline (speedup 1.0000x reference)
#include <cuda_runtime.h>
#include <math.h>

#define Bv 2
#define Lv 1024
#define Dv 768
#define Hv 12
#define DHv 64
#define Rv 256
#define ROWS (Bv*Lv)   // 2048
#define BHn (Bv*Hv)    // 24

// ---------------- scratch (device globals: allocation-free) ----------------
__device__ float g_xn[ROWS*Dv];                    // 6.3 MB
__device__ float g_qkv[(size_t)ROWS*3*Dv];         // 18.9 MB
__device__ float g_h1[ROWS*Rv];                    // 2.1 MB
__device__ float g_decay[BHn*Lv];
__device__ float g_gate[BHn*Lv];
__device__ float4 g_scal[BHn*Lv];                  // df, 1/(df+1e-8), gate*(1-decay), (1-decay)
__device__ float g_pacc[(size_t)ROWS*Hv*4*DHv];    // 25 MB  partial out_num (x df)
__device__ float g_qz[(size_t)ROWS*Hv*DHv];        // 6.3 MB q_f*z per d
__device__ float g_attn[ROWS*Dv];                  // 6.3 MB

// ---------------- reductions ----------------
__device__ __forceinline__ float block_sum_256(float v, float* s8){
  #pragma unroll
  for (int o=16;o>0;o>>=1) v += __shfl_xor_sync(0xffffffffu, v, o);
  if ((threadIdx.x&31)==0) s8[threadIdx.x>>5]=v;
  __syncthreads();
  float r = s8[0];
  #pragma unroll
  for (int i=1;i<8;i++) r += s8[i];
  __syncthreads();
  return r;
}

__device__ __forceinline__ float sum64(float v, float* s2){
  #pragma unroll
  for (int o=16;o>0;o>>=1) v += __shfl_xor_sync(0xffffffffu, v, o);
  if ((threadIdx.x&31)==0) s2[threadIdx.x>>5]=v;
  __syncthreads();
  float r = s2[0]+s2[1];
  __syncthreads();
  return r;
}

// ---------------- K1: causal depthwise conv(3) + residual + LayerNorm ----------------
__global__ void __launch_bounds__(256) conv_ln_kernel(const float* __restrict__ x,
    const float* __restrict__ cw, const float* __restrict__ cb,
    const float* __restrict__ lg, const float* __restrict__ lb){
  int row = blockIdx.x;           // b*L + l
  int l = row & (Lv-1);
  __shared__ float sxc[Dv];
  __shared__ float s8[8];
  int t = threadIdx.x;
  float sum = 0.f;
  #pragma unroll
  for (int i=0;i<3;i++){
    int d = t + i*256;
    float x0  = x[(size_t)row*Dv + d];
    float xm1 = (l>=1) ? x[(size_t)(row-1)*Dv + d] : 0.f;
    float xm2 = (l>=2) ? x[(size_t)(row-2)*Dv + d] : 0.f;
    float c = xm2*cw[d*3+0] + xm1*cw[d*3+1] + x0*cw[d*3+2] + cb[d];
    float xc = x0 + c;
    sxc[d] = xc;
    sum += xc;
  }
  float mu = block_sum_256(sum, s8) * (1.f/(float)Dv);
  float sq = 0.f;
  #pragma unroll
  for (int i=0;i<3;i++){ float dlt = sxc[t+i*256]-mu; sq += dlt*dlt; }
  float var = block_sum_256(sq, s8) * (1.f/(float)Dv);
  float inv = 1.f/sqrtf(var + 1e-5f);
  #pragma unroll
  for (int i=0;i<3;i++){
    int d = t+i*256;
    g_xn[(size_t)row*Dv+d] = (sxc[d]-mu)*inv*lg[d] + lb[d];
  }
}

// ---------------- generic fp32 NT GEMM: C[M,N] = A[M,K] @ B[N,K]^T (+bias | silu) ----------------
// ACT=0: +bias   ACT=1: silu, no bias
template<int ACT>
__global__ void __launch_bounds__(256) gemm_nt(const float* __restrict__ A,
    const float* __restrict__ Bm, const float* __restrict__ bias,
    float* __restrict__ C, int M, int N, int K){
  __shared__ __align__(16) float As[16][68];
  __shared__ __align__(16) float Bs[16][68];
  int t = threadIdx.x;
  int m0 = blockIdx.y*64, n0 = blockIdx.x*64;
  int lrow = t>>2, lc4 = (t&3)*4;
  int ty = t>>4, tx = t&15;
  float acc[4][4];
  #pragma unroll
  for (int i=0;i<4;i++)
    #pragma unroll
    for (int j=0;j<4;j++) acc[i][j]=0.f;
  const float* Ap = A  + (size_t)(m0+lrow)*K + lc4;
  const float* Bp = Bm + (size_t)(n0+lrow)*K + lc4;
  for (int k0=0;k0<K;k0+=16){
    float4 a4 = *(const float4*)(Ap+k0);
    float4 b4 = *(const float4*)(Bp+k0);
    __syncthreads();
    As[lc4+0][lrow]=a4.x; As[lc4+1][lrow]=a4.y; As[lc4+2][lrow]=a4.z; As[lc4+3][lrow]=a4.w;
    Bs[lc4+0][lrow]=b4.x; Bs[lc4+1][lrow]=b4.y; Bs[lc4+2][lrow]=b4.z; Bs[lc4+3][lrow]=b4.w;
    __syncthreads();
    #pragma unroll
    for (int k=0;k<16;k++){
      float4 av = *(const float4*)&As[k][ty*4];
      float4 bv = *(const float4*)&Bs[k][tx*4];
      acc[0][0]=fmaf(av.x,bv.x,acc[0][0]); acc[0][1]=fmaf(av.x,bv.y,acc[0][1]);
      acc[0][2]=fmaf(av.x,bv.z,acc[0][2]); acc[0][3]=fmaf(av.x,bv.w,acc[0][3]);
      acc[1][0]=fmaf(av.y,bv.x,acc[1][0]); acc[1][1]=fmaf(av.y,bv.y,acc[1][1]);
      acc[1][2]=fmaf(av.y,bv.z,acc[1][2]); acc[1][3]=fmaf(av.y,bv.w,acc[1][3]);
      acc[2][0]=fmaf(av.z,bv.x,acc[2][0]); acc[2][1]=fmaf(av.z,bv.y,acc[2][1]);
      acc[2][2]=fmaf(av.z,bv.z,acc[2][2]); acc[2][3]=fmaf(av.z,bv.w,acc[2][3]);
      acc[3][0]=fmaf(av.w,bv.x,acc[3][0]); acc[3][1]=fmaf(av.w,bv.y,acc[3][1]);
      acc[3][2]=fmaf(av.w,bv.z,acc[3][2]); acc[3][3]=fmaf(av.w,bv.w,acc[3][3]);
    }
  }
  #pragma unroll
  for (int i=0;i<4;i++){
    int m = m0+ty*4+i;
    #pragma unroll
    for (int j=0;j<4;j++){
      int n = n0+tx*4+j;
      float v = acc[i][j];
      if (ACT==0) v += bias[n];
      else        v = v/(1.f+expf(-v));     // silu
      C[(size_t)m*N+n]=v;
    }
  }
}

// ---------------- K4: params head (h1 @ bn_w2^T -> gate/decay) ----------------
__global__ void __launch_bounds__(64) params_kernel(const float* __restrict__ w2,
    const float* __restrict__ temp, float* __restrict__ out_gate){
  int row = blockIdx.x;
  int t = threadIdx.x;
  __shared__ float sh[Rv];
  __shared__ float sp[60];
  for (int i=t;i<Rv;i+=64) sh[i] = g_h1[(size_t)row*Rv+i];
  __syncthreads();
  if (t<60){
    const float* w = w2 + t*Rv;
    float a0=0.f;
    #pragma unroll 8
    for (int k=0;k<Rv;k++) a0 += sh[k]*w[k];
    sp[t]=a0;
  }
  __syncthreads();
  if (t<Hv){
    float p0=sp[t*5+0], p1=sp[t*5+1], p2=sp[t*5+2], p3=sp[t*5+3], p4=sp[t*5+4];
    const float PI = 3.14159265358979323846f;
    float sa  = 1.f/(1.f+expf(-p0));
    float sph = tanhf(p1)*PI;
    float ca  = 1.f/(1.f+expf(-p2));
    float cph = tanhf(p3)*PI;
    float dec = 0.3f + 0.65f*(1.f/(1.f+expf(-p4)));
    float gate = 1.f/(1.f+expf(-(sa*ca*cosf(sph-cph)*temp[0])));
    int b = row>>10;
    int l = row & (Lv-1);
    int idx = (b*Hv+t)*Lv + l;
    g_decay[idx]=dec; g_gate[idx]=gate;
    if (out_gate) out_gate[(size_t)row*Hv+t]=gate;
  }
}

// ---------------- K5: per-(b,h) cumsum(log decay) -> df, 1/safe_df, fused scalars ----------------
__global__ void __launch_bounds__(32) scanprep_kernel(){
  int bh = blockIdx.x;
  int lane = threadIdx.x;
  int base = bh*Lv;
  double carry = 0.0;
  for (int l0=0;l0<Lv;l0+=32){
    float dec  = g_decay[base+l0+lane];
    float gate = g_gate [base+l0+lane];
    float s = logf(dec);
    #pragma unroll
    for (int o=1;o<32;o<<=1){
      float nv = __shfl_up_sync(0xffffffffu, s, o);
      if (lane>=o) s += nv;
    }
    float ls = (float)(carry + (double)s);
    float df = expf(ls);
    g_scal[base+l0+lane] = make_float4(df, 1.f/(df+1e-8f), gate*(1.f-dec), 1.f-dec);
    float last = __shfl_sync(0xffffffffu, s, 31);
    carry += (double)last;
  }
}

// ---------------- K6: sequential linear-attention scan per (b,h) ----------------
// 24 blocks x 256 threads. thread = (e = t&63, dg = t>>6); 16 state regs (d range).
__global__ void __launch_bounds__(256) scan_kernel(){
  int bh = blockIdx.x;
  int b = bh/Hv, h = bh - b*Hv;
  int bL = b*Lv;
  int t = threadIdx.x;
  int e = t&63, dg = t>>6;
  __shared__ __align__(16) float sq[2][64];
  __shared__ __align__(16) float sk[2][64];
  __shared__ __align__(16) float sv[2][64];
  __shared__ float4 sscal[2];
  float C[16];
  #pragma unroll
  for (int i=0;i<16;i++) C[i]=0.f;
  float zc = 0.f;

  // preload l = 0
  {
    const float* qb = g_qkv + (size_t)bL*3*Dv;
    if (t<64)      { float q = qb[h*64+t];            sq[0][t]    = q>0.f ? q+1.f : expf(q); }
    else if (t<128){ int d=t-64;  float k = qb[Dv+h*64+d];   sk[0][d] = k>0.f ? k+1.f : expf(k); }
    else if (t<192){ int d=t-128; sv[0][d] = qb[2*Dv+h*64+d]; }
    else if (t==192){ sscal[0] = g_scal[bh*Lv]; }
  }
  __syncthreads();
  int p=0;
  for (int l=0;l<Lv;l++){
    if (l+1<Lv){  // prefetch next step into other buffer (safe: readers drained at prev sync)
      const float* qb = g_qkv + (size_t)(bL+l+1)*3*Dv;
      int pn = p^1;
      if (t<64)      { float q = qb[h*64+t];            sq[pn][t]    = q>0.f ? q+1.f : expf(q); }
      else if (t<128){ int d=t-64;  float k = qb[Dv+h*64+d];   sk[pn][d] = k>0.f ? k+1.f : expf(k); }
      else if (t<192){ int d=t-128; sv[pn][d] = qb[2*Dv+h*64+d]; }
      else if (t==192){ sscal[pn] = g_scal[bh*Lv + l + 1]; }
    }
    float4 sc = sscal[p];
    float vgo = sv[p][e]*sc.z;         // v_f[e] * gate * (1-decay)
    float inv = sc.y, df = sc.x;
    const float4* k4 = (const float4*)&sk[p][dg*16];
    const float4* q4 = (const float4*)&sq[p][dg*16];
    float a0=0.f,a1=0.f,a2=0.f,a3=0.f;
    #pragma unroll
    for (int j=0;j<4;j++){
      float4 kf = k4[j], qf = q4[j];
      float kv;
      kv = fminf(fmaxf(kf.x*vgo,-5.f),5.f); C[4*j+0]=fmaf(kv,inv,C[4*j+0]); a0=fmaf(qf.x,C[4*j+0],a0);
      kv = fminf(fmaxf(kf.y*vgo,-5.f),5.f); C[4*j+1]=fmaf(kv,inv,C[4*j+1]); a1=fmaf(qf.y,C[4*j+1],a1);
      kv = fminf(fmaxf(kf.z*vgo,-5.f),5.f); C[4*j+2]=fmaf(kv,inv,C[4*j+2]); a2=fmaf(qf.z,C[4*j+2],a2);
      kv = fminf(fmaxf(kf.w*vgo,-5.f),5.f); C[4*j+3]=fmaf(kv,inv,C[4*j+3]); a3=fmaf(qf.w,C[4*j+3],a3);
    }
    float acc = (a0+a1)+(a2+a3);
    g_pacc[(((size_t)(bL+l)*Hv + h)*4 + dg)*64 + e] = acc*df;
    if (dg==0){
      float kf = sk[p][e];                 // d = e
      zc = fmaf(kf*sc.w, inv, zc);         // k_f * (1-decay) / safe_df
      float z = zc*df;
      z = fminf(fmaxf(z,-10000.f),10000.f);
      g_qz[((size_t)(bL+l)*Hv + h)*64 + e] = sq[p][e]*z;
    }
    __syncthreads();
    p ^= 1;
  }
}

// ---------------- K7: den reduce + mini layernorm over e ----------------
__global__ void __launch_bounds__(64) finalize_kernel(const float* __restrict__ mg,
                                                      const float* __restrict__ mb){
  int id = blockIdx.x;     // row*Hv + h
  int e = threadIdx.x;
  __shared__ float s2[2];
  size_t base = (size_t)id*4*64;
  float num = g_pacc[base+e] + g_pacc[base+64+e] + g_pacc[base+128+e] + g_pacc[base+192+e];
  float qz  = g_qz[(size_t)id*64+e];
  float den = sum64(qz, s2) + 1e-4f;
  float val = num/den;
  float mu  = sum64(val, s2) * (1.f/64.f);
  float dlt = val - mu;
  float var = sum64(dlt*dlt, s2) * (1.f/64.f);
  float res = dlt/sqrtf(var+1e-5f)*mg[e] + mb[e];
  int row = id/Hv, h = id - row*Hv;
  g_attn[(size_t)row*Dv + h*64 + e] = res;
}

// ---------------- launch ----------------
extern "C" void kernel_launch(void* const* d_in, const int* in_sizes, int n_in,
                              void* d_out, int out_size){
  const float* x      = (const float*)d_in[0];
  const float* conv_w = (const float*)d_in[1];
  const float* conv_b = (const float*)d_in[2];
  const float* ln_g   = (const float*)d_in[3];
  const float* ln_b   = (const float*)d_in[4];
  const float* qkv_w  = (const float*)d_in[5];
  const float* qkv_b  = (const float*)d_in[6];
  const float* bn_w1  = (const float*)d_in[7];
  const float* bn_w2  = (const float*)d_in[8];
  const float* temp   = (const float*)d_in[9];
  const float* proj_w = (const float*)d_in[10];
  const float* proj_b = (const float*)d_in[11];
  const float* mn_g   = (const float*)d_in[12];
  const float* mn_b   = (const float*)d_in[13];
  float* out = (float*)d_out;
  float* gate_out = ((size_t)out_size >= (size_t)ROWS*Dv + (size_t)ROWS*Hv)
                    ? out + (size_t)ROWS*Dv : nullptr;

  void *p_xn, *p_qkv, *p_h1, *p_attn;
  cudaGetSymbolAddress(&p_xn,  g_xn);
  cudaGetSymbolAddress(&p_qkv, g_qkv);
  cudaGetSymbolAddress(&p_h1,  g_h1);
  cudaGetSymbolAddress(&p_attn,g_attn);

  conv_ln_kernel<<<ROWS,256>>>(x, conv_w, conv_b, ln_g, ln_b);
  gemm_nt<0><<<dim3((3*Dv)/64, ROWS/64),256>>>((const float*)p_xn, qkv_w, qkv_b,
                                               (float*)p_qkv, ROWS, 3*Dv, Dv);
  gemm_nt<1><<<dim3(Rv/64, ROWS/64),256>>>((const float*)p_xn, bn_w1, nullptr,
                                           (float*)p_h1, ROWS, Rv, Dv);
  params_kernel<<<ROWS,64>>>(bn_w2, temp, gate_out);
  scanprep_kernel<<<BHn,32>>>();
  scan_kernel<<<BHn,256>>>();
  finalize_kernel<<<ROWS*Hv,64>>>(mn_g, mn_b);
  gemm_nt<0><<<dim3(Dv/64, ROWS/64),256>>>((const float*)p_attn, proj_w, proj_b,
                                           out, ROWS, Dv, Dv);
}

// round 3
// speedup vs baseline: 2.3181x; 2.3181x over previous
#include <cuda_runtime.h>
#include <math.h>

#define Bv 2
#define Lv 1024
#define Dv 768
#define Hv 12
#define DHv 64
#define Rv 256
#define ROWS (Bv*Lv)   // 2048
#define BHn (Bv*Hv)    // 24
#define CH 32          // scan chunks
#define Tc 32          // steps per chunk

// ---------------- scratch (device globals: allocation-free) ----------------
__device__ float g_xn[ROWS*Dv];                    // 6.3 MB
__device__ float g_qkv[(size_t)ROWS*3*Dv];         // 18.9 MB
__device__ float g_h1[ROWS*Rv];                    // 2.1 MB
__device__ float g_P[ROWS*64];                     // 0.5 MB params GEMM out (ldc=64)
__device__ float g_decay[BHn*Lv];
__device__ float g_gate[BHn*Lv];
__device__ float4 g_scal[BHn*Lv];                  // df, 1/(df+1e-8), gate*(1-decay), (1-decay)
__device__ float g_csum[(size_t)BHn*CH*DHv*DHv];   // 12.6 MB per-chunk local state sums
__device__ float g_carry[(size_t)BHn*CH*DHv*DHv];  // 12.6 MB exclusive chunk prefixes
__device__ float g_zsum[BHn*CH*DHv];
__device__ float g_zcarry[BHn*CH*DHv];
__device__ float g_pacc[(size_t)ROWS*Hv*4*DHv];    // 25 MB  partial out_num (x df)
__device__ float g_qz[(size_t)ROWS*Hv*DHv];        // 6.3 MB q_f*z per d
__device__ float g_attn[ROWS*Dv];                  // 6.3 MB

// ---------------- reductions ----------------
__device__ __forceinline__ float block_sum_256(float v, float* s8){
  #pragma unroll
  for (int o=16;o>0;o>>=1) v += __shfl_xor_sync(0xffffffffu, v, o);
  if ((threadIdx.x&31)==0) s8[threadIdx.x>>5]=v;
  __syncthreads();
  float r = s8[0];
  #pragma unroll
  for (int i=1;i<8;i++) r += s8[i];
  __syncthreads();
  return r;
}

__device__ __forceinline__ float sum64(float v, float* s2){
  #pragma unroll
  for (int o=16;o>0;o>>=1) v += __shfl_xor_sync(0xffffffffu, v, o);
  if ((threadIdx.x&31)==0) s2[threadIdx.x>>5]=v;
  __syncthreads();
  float r = s2[0]+s2[1];
  __syncthreads();
  return r;
}

// ---------------- K1: causal depthwise conv(3) + residual + LayerNorm ----------------
__global__ void __launch_bounds__(256) conv_ln_kernel(const float* __restrict__ x,
    const float* __restrict__ cw, const float* __restrict__ cb,
    const float* __restrict__ lg, const float* __restrict__ lb){
  int row = blockIdx.x;           // b*L + l
  int l = row & (Lv-1);
  __shared__ float sxc[Dv];
  __shared__ float s8[8];
  int t = threadIdx.x;
  float sum = 0.f;
  #pragma unroll
  for (int i=0;i<3;i++){
    int d = t + i*256;
    float x0  = x[(size_t)row*Dv + d];
    float xm1 = (l>=1) ? x[(size_t)(row-1)*Dv + d] : 0.f;
    float xm2 = (l>=2) ? x[(size_t)(row-2)*Dv + d] : 0.f;
    float c = xm2*cw[d*3+0] + xm1*cw[d*3+1] + x0*cw[d*3+2] + cb[d];
    float xc = x0 + c;
    sxc[d] = xc;
    sum += xc;
  }
  float mu = block_sum_256(sum, s8) * (1.f/(float)Dv);
  float sq = 0.f;
  #pragma unroll
  for (int i=0;i<3;i++){ float dlt = sxc[t+i*256]-mu; sq += dlt*dlt; }
  float var = block_sum_256(sq, s8) * (1.f/(float)Dv);
  float inv = 1.f/sqrtf(var + 1e-5f);
  #pragma unroll
  for (int i=0;i<3;i++){
    int d = t+i*256;
    g_xn[(size_t)row*Dv+d] = (sxc[d]-mu)*inv*lg[d] + lb[d];
  }
}

// ---------------- fp32 NT GEMM 64x64 tile: C[M,N] = A[M,K] @ B[N,K]^T ----------------
// ACT=0: +bias (bias may be null)   ACT=1: silu, no bias.  N-edge guarded, ldc separate.
template<int ACT>
__global__ void __launch_bounds__(256) gemm_nt(const float* __restrict__ A,
    const float* __restrict__ Bm, const float* __restrict__ bias,
    float* __restrict__ C, int M, int N, int K, int ldc){
  __shared__ __align__(16) float As[16][68];
  __shared__ __align__(16) float Bs[16][68];
  int t = threadIdx.x;
  int m0 = blockIdx.y*64, n0 = blockIdx.x*64;
  int lrow = t>>2, lc4 = (t&3)*4;
  int ty = t>>4, tx = t&15;
  float acc[4][4];
  #pragma unroll
  for (int i=0;i<4;i++)
    #pragma unroll
    for (int j=0;j<4;j++) acc[i][j]=0.f;
  const float* Ap = A  + (size_t)(m0+lrow)*K + lc4;
  const float* Bp = Bm + (size_t)(n0+lrow)*K + lc4;
  bool bok = (n0+lrow) < N;
  for (int k0=0;k0<K;k0+=16){
    float4 a4 = *(const float4*)(Ap+k0);
    float4 b4 = bok ? *(const float4*)(Bp+k0) : make_float4(0.f,0.f,0.f,0.f);
    __syncthreads();
    As[lc4+0][lrow]=a4.x; As[lc4+1][lrow]=a4.y; As[lc4+2][lrow]=a4.z; As[lc4+3][lrow]=a4.w;
    Bs[lc4+0][lrow]=b4.x; Bs[lc4+1][lrow]=b4.y; Bs[lc4+2][lrow]=b4.z; Bs[lc4+3][lrow]=b4.w;
    __syncthreads();
    #pragma unroll
    for (int k=0;k<16;k++){
      float4 av = *(const float4*)&As[k][ty*4];
      float4 bv = *(const float4*)&Bs[k][tx*4];
      acc[0][0]=fmaf(av.x,bv.x,acc[0][0]); acc[0][1]=fmaf(av.x,bv.y,acc[0][1]);
      acc[0][2]=fmaf(av.x,bv.z,acc[0][2]); acc[0][3]=fmaf(av.x,bv.w,acc[0][3]);
      acc[1][0]=fmaf(av.y,bv.x,acc[1][0]); acc[1][1]=fmaf(av.y,bv.y,acc[1][1]);
      acc[1][2]=fmaf(av.y,bv.z,acc[1][2]); acc[1][3]=fmaf(av.y,bv.w,acc[1][3]);
      acc[2][0]=fmaf(av.z,bv.x,acc[2][0]); acc[2][1]=fmaf(av.z,bv.y,acc[2][1]);
      acc[2][2]=fmaf(av.z,bv.z,acc[2][2]); acc[2][3]=fmaf(av.z,bv.w,acc[2][3]);
      acc[3][0]=fmaf(av.w,bv.x,acc[3][0]); acc[3][1]=fmaf(av.w,bv.y,acc[3][1]);
      acc[3][2]=fmaf(av.w,bv.z,acc[3][2]); acc[3][3]=fmaf(av.w,bv.w,acc[3][3]);
    }
  }
  #pragma unroll
  for (int i=0;i<4;i++){
    int m = m0+ty*4+i;
    #pragma unroll
    for (int j=0;j<4;j++){
      int n = n0+tx*4+j;
      if (n < N){
        float v = acc[i][j];
        if (ACT==0) v += (bias ? bias[n] : 0.f);
        else        v = v/(1.f+expf(-v));     // silu
        C[(size_t)m*ldc+n]=v;
      }
    }
  }
}

// ---------------- fp32 NT GEMM 128x128 tile, 8x8 micro (dims multiples of 128) -----
__global__ void __launch_bounds__(256) gemm128(const float* __restrict__ A,
    const float* __restrict__ Bm, const float* __restrict__ bias,
    float* __restrict__ C, int M, int N, int K){
  __shared__ __align__(16) float As[16][132];
  __shared__ __align__(16) float Bs[16][132];
  int t = threadIdx.x;
  int m0 = blockIdx.y*128, n0 = blockIdx.x*128;
  int lm = t>>2;            // 0..63
  int lk = (t&3)*4;         // 0,4,8,12
  int ty = t>>4, tx = t&15;
  float acc[8][8];
  #pragma unroll
  for (int i=0;i<8;i++)
    #pragma unroll
    for (int j=0;j<8;j++) acc[i][j]=0.f;
  const float* Ap = A  + (size_t)(m0+lm)*K + lk;
  const float* Bp = Bm + (size_t)(n0+lm)*K + lk;
  for (int k0=0;k0<K;k0+=16){
    float4 a0 = *(const float4*)(Ap+k0);
    float4 a1 = *(const float4*)(Ap+(size_t)64*K+k0);
    float4 b0 = *(const float4*)(Bp+k0);
    float4 b1 = *(const float4*)(Bp+(size_t)64*K+k0);
    __syncthreads();
    As[lk+0][lm]=a0.x; As[lk+1][lm]=a0.y; As[lk+2][lm]=a0.z; As[lk+3][lm]=a0.w;
    As[lk+0][lm+64]=a1.x; As[lk+1][lm+64]=a1.y; As[lk+2][lm+64]=a1.z; As[lk+3][lm+64]=a1.w;
    Bs[lk+0][lm]=b0.x; Bs[lk+1][lm]=b0.y; Bs[lk+2][lm]=b0.z; Bs[lk+3][lm]=b0.w;
    Bs[lk+0][lm+64]=b1.x; Bs[lk+1][lm+64]=b1.y; Bs[lk+2][lm+64]=b1.z; Bs[lk+3][lm+64]=b1.w;
    __syncthreads();
    #pragma unroll
    for (int k=0;k<16;k++){
      float4 av0 = *(const float4*)&As[k][ty*8];
      float4 av1 = *(const float4*)&As[k][ty*8+4];
      float4 bv0 = *(const float4*)&Bs[k][tx*8];
      float4 bv1 = *(const float4*)&Bs[k][tx*8+4];
      float ar[8]={av0.x,av0.y,av0.z,av0.w,av1.x,av1.y,av1.z,av1.w};
      float br[8]={bv0.x,bv0.y,bv0.z,bv0.w,bv1.x,bv1.y,bv1.z,bv1.w};
      #pragma unroll
      for (int i=0;i<8;i++)
        #pragma unroll
        for (int j=0;j<8;j++) acc[i][j]=fmaf(ar[i],br[j],acc[i][j]);
    }
  }
  #pragma unroll
  for (int i=0;i<8;i++){
    int m = m0+ty*8+i;
    #pragma unroll
    for (int j=0;j<8;j++){
      int n = n0+tx*8+j;
      C[(size_t)m*N+n]=acc[i][j]+bias[n];
    }
  }
}

// ---------------- params elementwise: P -> gate/decay ----------------
__global__ void __launch_bounds__(256) params_elem(const float* __restrict__ temp,
                                                   float* __restrict__ out_gate){
  int idx = blockIdx.x*256 + threadIdx.x;
  if (idx >= ROWS*Hv) return;
  int row = idx/Hv, h = idx - row*Hv;
  const float* sp = g_P + (size_t)row*64 + h*5;
  float p0=sp[0], p1=sp[1], p2=sp[2], p3=sp[3], p4=sp[4];
  const float PI = 3.14159265358979323846f;
  float sa  = 1.f/(1.f+expf(-p0));
  float sph = tanhf(p1)*PI;
  float ca  = 1.f/(1.f+expf(-p2));
  float cph = tanhf(p3)*PI;
  float dec = 0.3f + 0.65f*(1.f/(1.f+expf(-p4)));
  float gate = 1.f/(1.f+expf(-(sa*ca*cosf(sph-cph)*temp[0])));
  int b = row>>10;
  int l = row & (Lv-1);
  int o = (b*Hv+h)*Lv + l;
  g_decay[o]=dec; g_gate[o]=gate;
  if (out_gate) out_gate[idx]=gate;
}

// ---------------- per-(b,h) cumsum(log decay) -> fused scalars ----------------
__global__ void __launch_bounds__(32) scanprep_kernel(){
  int bh = blockIdx.x;
  int lane = threadIdx.x;
  int base = bh*Lv;
  double carry = 0.0;
  for (int l0=0;l0<Lv;l0+=32){
    float dec  = g_decay[base+l0+lane];
    float gate = g_gate [base+l0+lane];
    float s = logf(dec);
    #pragma unroll
    for (int o=1;o<32;o<<=1){
      float nv = __shfl_up_sync(0xffffffffu, s, o);
      if (lane>=o) s += nv;
    }
    float ls = (float)(carry + (double)s);
    float df = expf(ls);
    g_scal[base+l0+lane] = make_float4(df, 1.f/(df+1e-8f), gate*(1.f-dec), 1.f-dec);
    float last = __shfl_sync(0xffffffffu, s, 31);
    carry += (double)last;
  }
}

// ---------------- scan pass 1: per-chunk local state sums ----------------
// grid = BHn*CH blocks; blockIdx.x = bh*CH + c
__global__ void __launch_bounds__(256) scan_partial(){
  int blk = blockIdx.x;
  int bh = blk>>5, c = blk&(CH-1);
  int b = bh/Hv, h = bh - b*Hv;
  int base = b*Lv + c*Tc;     // global row of first step
  int t = threadIdx.x, e = t&63, dg = t>>6;
  __shared__ __align__(16) float sk[2][64];
  __shared__ __align__(16) float sv[2][64];
  __shared__ float4 sscal[2];
  float C[16];
  #pragma unroll
  for (int j=0;j<16;j++) C[j]=0.f;
  float zc = 0.f;
  {
    const float* qb = g_qkv + (size_t)base*3*Dv;
    if (t<64)       { float k = qb[Dv+h*64+t];      sk[0][t]    = k>0.f ? k+1.f : expf(k); }
    else if (t<128) { sv[0][t-64] = qb[2*Dv+h*64+(t-64)]; }
    else if (t==128){ sscal[0] = g_scal[bh*Lv + c*Tc]; }
  }
  __syncthreads();
  int p=0;
  for (int i=0;i<Tc;i++){
    if (i+1<Tc){
      const float* qb = g_qkv + (size_t)(base+i+1)*3*Dv;
      int pn=p^1;
      if (t<64)       { float k = qb[Dv+h*64+t];      sk[pn][t]    = k>0.f ? k+1.f : expf(k); }
      else if (t<128) { sv[pn][t-64] = qb[2*Dv+h*64+(t-64)]; }
      else if (t==128){ sscal[pn] = g_scal[bh*Lv + c*Tc + i + 1]; }
    }
    float4 sc = sscal[p];
    float vgo = sv[p][e]*sc.z;
    float inv = sc.y;
    const float4* k4 = (const float4*)&sk[p][dg*16];
    #pragma unroll
    for (int j=0;j<4;j++){
      float4 kf = k4[j];
      float kv;
      kv = fminf(fmaxf(kf.x*vgo,-5.f),5.f); C[4*j+0]=fmaf(kv,inv,C[4*j+0]);
      kv = fminf(fmaxf(kf.y*vgo,-5.f),5.f); C[4*j+1]=fmaf(kv,inv,C[4*j+1]);
      kv = fminf(fmaxf(kf.z*vgo,-5.f),5.f); C[4*j+2]=fmaf(kv,inv,C[4*j+2]);
      kv = fminf(fmaxf(kf.w*vgo,-5.f),5.f); C[4*j+3]=fmaf(kv,inv,C[4*j+3]);
    }
    if (dg==0){
      zc = fmaf(sk[p][e]*sc.w, inv, zc);
    }
    __syncthreads();
    p ^= 1;
  }
  size_t o = (size_t)blk*4096 + (size_t)dg*16*64 + e;
  #pragma unroll
  for (int j=0;j<16;j++) g_csum[o + j*64] = C[j];
  if (dg==0) g_zsum[blk*64+e] = zc;
}

// ---------------- scan pass 1.5: exclusive chunk prefixes per bh ----------------
__global__ void __launch_bounds__(256) scan_combine(){
  int bh = blockIdx.x;
  int t = threadIdx.x, e = t&63, dg = t>>6;
  float acc[16];
  #pragma unroll
  for (int j=0;j<16;j++) acc[j]=0.f;
  float zacc = 0.f;
  for (int c=0;c<CH;c++){
    int blk = bh*CH + c;
    size_t o = (size_t)blk*4096 + (size_t)dg*16*64 + e;
    #pragma unroll
    for (int j=0;j<16;j++){
      float s = g_csum[o + j*64];
      g_carry[o + j*64] = acc[j];
      acc[j] += s;
    }
    if (dg==0){
      g_zcarry[blk*64+e] = zacc;
      zacc += g_zsum[blk*64+e];
    }
  }
}

// ---------------- scan pass 2: carry-initialized sequential scan + outputs ----------------
__global__ void __launch_bounds__(256) scan_main(){
  int blk = blockIdx.x;
  int bh = blk>>5, c = blk&(CH-1);
  int b = bh/Hv, h = bh - b*Hv;
  int base = b*Lv + c*Tc;
  int t = threadIdx.x, e = t&63, dg = t>>6;
  __shared__ __align__(16) float sq[2][64];
  __shared__ __align__(16) float sk[2][64];
  __shared__ __align__(16) float sv[2][64];
  __shared__ float4 sscal[2];
  float C[16];
  {
    size_t o = (size_t)blk*4096 + (size_t)dg*16*64 + e;
    #pragma unroll
    for (int j=0;j<16;j++) C[j] = g_carry[o + j*64];
  }
  float zc = g_zcarry[blk*64+e];   // meaningful only for dg==0
  {
    const float* qb = g_qkv + (size_t)base*3*Dv;
    if (t<64)       { float q = qb[h*64+t];          sq[0][t]    = q>0.f ? q+1.f : expf(q); }
    else if (t<128) { int d=t-64;  float k = qb[Dv+h*64+d];  sk[0][d] = k>0.f ? k+1.f : expf(k); }
    else if (t<192) { int d=t-128; sv[0][d] = qb[2*Dv+h*64+d]; }
    else if (t==192){ sscal[0] = g_scal[bh*Lv + c*Tc]; }
  }
  __syncthreads();
  int p=0;
  for (int i=0;i<Tc;i++){
    if (i+1<Tc){
      const float* qb = g_qkv + (size_t)(base+i+1)*3*Dv;
      int pn=p^1;
      if (t<64)       { float q = qb[h*64+t];          sq[pn][t]    = q>0.f ? q+1.f : expf(q); }
      else if (t<128) { int d=t-64;  float k = qb[Dv+h*64+d];  sk[pn][d] = k>0.f ? k+1.f : expf(k); }
      else if (t<192) { int d=t-128; sv[pn][d] = qb[2*Dv+h*64+d]; }
      else if (t==192){ sscal[pn] = g_scal[bh*Lv + c*Tc + i + 1]; }
    }
    float4 sc = sscal[p];
    float vgo = sv[p][e]*sc.z;
    float inv = sc.y, df = sc.x;
    const float4* k4 = (const float4*)&sk[p][dg*16];
    const float4* q4 = (const float4*)&sq[p][dg*16];
    float a0=0.f,a1=0.f,a2=0.f,a3=0.f;
    #pragma unroll
    for (int j=0;j<4;j++){
      float4 kf = k4[j], qf = q4[j];
      float kv;
      kv = fminf(fmaxf(kf.x*vgo,-5.f),5.f); C[4*j+0]=fmaf(kv,inv,C[4*j+0]); a0=fmaf(qf.x,C[4*j+0],a0);
      kv = fminf(fmaxf(kf.y*vgo,-5.f),5.f); C[4*j+1]=fmaf(kv,inv,C[4*j+1]); a1=fmaf(qf.y,C[4*j+1],a1);
      kv = fminf(fmaxf(kf.z*vgo,-5.f),5.f); C[4*j+2]=fmaf(kv,inv,C[4*j+2]); a2=fmaf(qf.z,C[4*j+2],a2);
      kv = fminf(fmaxf(kf.w*vgo,-5.f),5.f); C[4*j+3]=fmaf(kv,inv,C[4*j+3]); a3=fmaf(qf.w,C[4*j+3],a3);
    }
    float acc = (a0+a1)+(a2+a3);
    int row = base + i;
    g_pacc[(((size_t)row*Hv + h)*4 + dg)*64 + e] = acc*df;
    if (dg==0){
      zc = fmaf(sk[p][e]*sc.w, inv, zc);
      float z = zc*df;
      z = fminf(fmaxf(z,-10000.f),10000.f);
      g_qz[((size_t)row*Hv + h)*64 + e] = sq[p][e]*z;
    }
    __syncthreads();
    p ^= 1;
  }
}

// ---------------- finalize: den reduce + mini layernorm over e ----------------
__global__ void __launch_bounds__(64) finalize_kernel(const float* __restrict__ mg,
                                                      const float* __restrict__ mb){
  int id = blockIdx.x;     // row*Hv + h
  int e = threadIdx.x;
  __shared__ float s2[2];
  size_t base = (size_t)id*4*64;
  float num = g_pacc[base+e] + g_pacc[base+64+e] + g_pacc[base+128+e] + g_pacc[base+192+e];
  float qz  = g_qz[(size_t)id*64+e];
  float den = sum64(qz, s2) + 1e-4f;
  float val = num/den;
  float mu  = sum64(val, s2) * (1.f/64.f);
  float dlt = val - mu;
  float var = sum64(dlt*dlt, s2) * (1.f/64.f);
  float res = dlt/sqrtf(var+1e-5f)*mg[e] + mb[e];
  int row = id/Hv, h = id - row*Hv;
  g_attn[(size_t)row*Dv + h*64 + e] = res;
}

// ---------------- launch ----------------
extern "C" void kernel_launch(void* const* d_in, const int* in_sizes, int n_in,
                              void* d_out, int out_size){
  const float* x      = (const float*)d_in[0];
  const float* conv_w = (const float*)d_in[1];
  const float* conv_b = (const float*)d_in[2];
  const float* ln_g   = (const float*)d_in[3];
  const float* ln_b   = (const float*)d_in[4];
  const float* qkv_w  = (const float*)d_in[5];
  const float* qkv_b  = (const float*)d_in[6];
  const float* bn_w1  = (const float*)d_in[7];
  const float* bn_w2  = (const float*)d_in[8];
  const float* temp   = (const float*)d_in[9];
  const float* proj_w = (const float*)d_in[10];
  const float* proj_b = (const float*)d_in[11];
  const float* mn_g   = (const float*)d_in[12];
  const float* mn_b   = (const float*)d_in[13];
  float* out = (float*)d_out;
  float* gate_out = ((size_t)out_size >= (size_t)ROWS*Dv + (size_t)ROWS*Hv)
                    ? out + (size_t)ROWS*Dv : nullptr;

  void *p_xn, *p_qkv, *p_h1, *p_P, *p_attn;
  cudaGetSymbolAddress(&p_xn,  g_xn);
  cudaGetSymbolAddress(&p_qkv, g_qkv);
  cudaGetSymbolAddress(&p_h1,  g_h1);
  cudaGetSymbolAddress(&p_P,   g_P);
  cudaGetSymbolAddress(&p_attn,g_attn);

  conv_ln_kernel<<<ROWS,256>>>(x, conv_w, conv_b, ln_g, ln_b);
  // QKV: 2048x2304x768
  gemm128<<<dim3((3*Dv)/128, ROWS/128),256>>>((const float*)p_xn, qkv_w, qkv_b,
                                              (float*)p_qkv, ROWS, 3*Dv, Dv);
  // bottleneck h1 = silu(xn @ bn_w1^T): 2048x256x768
  gemm_nt<1><<<dim3(Rv/64, ROWS/64),256>>>((const float*)p_xn, bn_w1, nullptr,
                                           (float*)p_h1, ROWS, Rv, Dv, Rv);
  // params P = h1 @ bn_w2^T: 2048x60x256 (ldc=64)
  gemm_nt<0><<<dim3(1, ROWS/64),256>>>((const float*)p_h1, bn_w2, nullptr,
                                       (float*)p_P, ROWS, Hv*5, Rv, 64);
  params_elem<<<(ROWS*Hv+255)/256,256>>>(temp, gate_out);
  scanprep_kernel<<<BHn,32>>>();
  scan_partial<<<BHn*CH,256>>>();
  scan_combine<<<BHn,256>>>();
  scan_main<<<BHn*CH,256>>>();
  finalize_kernel<<<ROWS*Hv,64>>>(mn_g, mn_b);
  // proj: 2048x768x768
  gemm_nt<0><<<dim3(Dv/64, ROWS/64),256>>>((const float*)p_attn, proj_w, proj_b,
                                           out, ROWS, Dv, Dv, Dv);
}

// round 10
// speedup vs baseline: 3.0397x; 1.3113x over previous
#include <cuda_runtime.h>
#include <cuda_bf16.h>
#include <math.h>
#include <stdint.h>
#include <stddef.h>

#define Bv 2
#define Lv 1024
#define Dv 768
#define Hv 12
#define DHv 64
#define Rv 256
#define ROWS (Bv*Lv)   // 2048
#define BHn (Bv*Hv)    // 24
#define CH 32          // scan chunks
#define Tc 32          // steps per chunk

// ---------------- scratch (device globals: allocation-free) ----------------
__device__ float g_xn[ROWS*Dv];
__device__ float g_qkv[(size_t)ROWS*3*Dv];
__device__ float g_h1[ROWS*Rv];
__device__ float g_P[ROWS*64];
__device__ float g_decay[BHn*Lv];
__device__ float g_gate[BHn*Lv];
__device__ float4 g_scal[BHn*Lv];                  // df, 1/(df+1e-8), gate*(1-dec), (1-dec)
__device__ float g_csum[(size_t)BHn*CH*DHv*DHv];
__device__ float g_carry[(size_t)BHn*CH*DHv*DHv];
__device__ float g_zsum[BHn*CH*DHv];
__device__ float g_zcarry[BHn*CH*DHv];
__device__ float g_pacc[(size_t)ROWS*Hv*4*DHv];
__device__ float g_qz[(size_t)ROWS*Hv*DHv];
__device__ float g_attn[ROWS*Dv];

// ---------------- reductions ----------------
__device__ __forceinline__ float block_sum_256(float v, float* s8){
  #pragma unroll
  for (int o=16;o>0;o>>=1) v += __shfl_xor_sync(0xffffffffu, v, o);
  if ((threadIdx.x&31)==0) s8[threadIdx.x>>5]=v;
  __syncthreads();
  float r = s8[0];
  #pragma unroll
  for (int i=1;i<8;i++) r += s8[i];
  __syncthreads();
  return r;
}

__device__ __forceinline__ float sum64(float v, float* s2){
  #pragma unroll
  for (int o=16;o>0;o>>=1) v += __shfl_xor_sync(0xffffffffu, v, o);
  if ((threadIdx.x&31)==0) s2[threadIdx.x>>5]=v;
  __syncthreads();
  float r = s2[0]+s2[1];
  __syncthreads();
  return r;
}

// ---------------- K1: causal depthwise conv(3) + residual + LayerNorm ----------------
__global__ void __launch_bounds__(256) conv_ln_kernel(const float* __restrict__ x,
    const float* __restrict__ cw, const float* __restrict__ cb,
    const float* __restrict__ lg, const float* __restrict__ lb){
  int row = blockIdx.x;
  int l = row & (Lv-1);
  __shared__ float sxc[Dv];
  __shared__ float s8[8];
  int t = threadIdx.x;
  float sum = 0.f;
  #pragma unroll
  for (int i=0;i<3;i++){
    int d = t + i*256;
    float x0  = x[(size_t)row*Dv + d];
    float xm1 = (l>=1) ? x[(size_t)(row-1)*Dv + d] : 0.f;
    float xm2 = (l>=2) ? x[(size_t)(row-2)*Dv + d] : 0.f;
    float c = xm2*cw[d*3+0] + xm1*cw[d*3+1] + x0*cw[d*3+2] + cb[d];
    float xc = x0 + c;
    sxc[d] = xc;
    sum += xc;
  }
  float mu = block_sum_256(sum, s8) * (1.f/(float)Dv);
  float sq = 0.f;
  #pragma unroll
  for (int i=0;i<3;i++){ float dlt = sxc[t+i*256]-mu; sq += dlt*dlt; }
  float var = block_sum_256(sq, s8) * (1.f/(float)Dv);
  float inv = 1.f/sqrtf(var + 1e-5f);
  #pragma unroll
  for (int i=0;i<3;i++){
    int d = t+i*256;
    g_xn[(size_t)row*Dv+d] = (sxc[d]-mu)*inv*lg[d] + lb[d];
  }
}

// ================= tensor-core GEMM (bf16 3-term split, fp32 acc) =================
// C[M,N] = A[M,K] @ B[N,K]^T  ; tile 128(M) x 64(N) x 16(K); 256 threads (8 warps 4x2)
// ACT=0: +bias (bias may be null)  ACT=1: silu
// Nb = valid B rows (rows >= Nb read as zero)

__device__ __forceinline__ uint32_t smaddr(const void* p){
  return (uint32_t)__cvta_generic_to_shared(p);
}
__device__ __forceinline__ uint32_t packbf(__nv_bfloat16 a, __nv_bfloat16 b){
  return (uint32_t)__bfloat16_as_ushort(a) | ((uint32_t)__bfloat16_as_ushort(b)<<16);
}
__device__ __forceinline__ void cvt4(float4 v, uint2& hi, uint2& lo){
  __nv_bfloat16 hx=__float2bfloat16_rn(v.x), hy=__float2bfloat16_rn(v.y);
  __nv_bfloat16 hz=__float2bfloat16_rn(v.z), hw=__float2bfloat16_rn(v.w);
  __nv_bfloat16 lx=__float2bfloat16_rn(v.x-__bfloat162float(hx));
  __nv_bfloat16 ly=__float2bfloat16_rn(v.y-__bfloat162float(hy));
  __nv_bfloat16 lz=__float2bfloat16_rn(v.z-__bfloat162float(hz));
  __nv_bfloat16 lw=__float2bfloat16_rn(v.w-__bfloat162float(hw));
  hi.x = packbf(hx,hy); hi.y = packbf(hz,hw);
  lo.x = packbf(lx,ly); lo.y = packbf(lz,lw);
}
__device__ __forceinline__ void ldmx4(uint32_t a, uint32_t* r){
  asm volatile("ldmatrix.sync.aligned.m8n8.x4.shared.b16 {%0,%1,%2,%3}, [%4];"
    : "=r"(r[0]),"=r"(r[1]),"=r"(r[2]),"=r"(r[3]) : "r"(a));
}
__device__ __forceinline__ void mma16816(float* c, const uint32_t* a, uint32_t b0, uint32_t b1){
  asm volatile("mma.sync.aligned.m16n8k16.row.col.f32.bf16.bf16.f32 "
    "{%0,%1,%2,%3}, {%4,%5,%6,%7}, {%8,%9}, {%0,%1,%2,%3};"
    : "+f"(c[0]),"+f"(c[1]),"+f"(c[2]),"+f"(c[3])
    : "r"(a[0]),"r"(a[1]),"r"(a[2]),"r"(a[3]), "r"(b0),"r"(b1));
}

#define SA 24                    // smem row stride in bf16 (48B: conflict-free ldmatrix)
#define OF_AHI 0
#define OF_ALO 3072
#define OF_BHI 6144
#define OF_BLO 7680
#define STG 9216

template<int ACT>
__global__ void __launch_bounds__(256) gemm_tc(const float* __restrict__ A,
    const float* __restrict__ Bm, const float* __restrict__ bias,
    float* __restrict__ C, int K, int ldc, int Nb){
  __shared__ __align__(16) __nv_bfloat16 sm[2][STG];
  int t = threadIdx.x;
  int m0 = blockIdx.y*128, n0 = blockIdx.x*64;
  int lane = t&31, wid = t>>5;
  int wm = wid&3, wn = wid>>2;

  // loader indices
  int arow = t>>2, acol = (t&3)*4;
  const float* Ap0 = A + (size_t)(m0+arow)*K + acol;
  const float* Ap1 = A + (size_t)(m0+arow+64)*K + acol;
  bool bok = (n0+arow) < Nb;
  const float* Bp = Bm + (size_t)(n0+arow)*K + acol;

  float acc[2][4][4];
  #pragma unroll
  for (int i=0;i<2;i++)
    #pragma unroll
    for (int j=0;j<4;j++)
      #pragma unroll
      for (int q=0;q<4;q++) acc[i][j][q]=0.f;

  float4 a4_0 = *(const float4*)(Ap0);
  float4 a4_1 = *(const float4*)(Ap1);
  float4 b4   = bok ? *(const float4*)(Bp) : make_float4(0.f,0.f,0.f,0.f);

  // precompute ldmatrix smem offsets (element units within a stage)
  int a_off0 = (wm*32 + (lane&15))*SA + (lane>>4)*8;          // mt=0
  int a_off1 = a_off0 + 16*SA;                                 // mt=1
  int b_r    = wn*32 + (lane&7) + ((lane>>4)<<3);
  int b_c    = ((lane>>3)&1)*8;
  int b_off0 = b_r*SA + b_c;                                   // pair 0 (ntiles 0,1)
  int b_off1 = (b_r+16)*SA + b_c;                              // pair 1 (ntiles 2,3)

  int nIter = K>>4;
  int p = 0;
  // store first tile
  {
    uint2 hi,lo;
    __nv_bfloat16* s = sm[0];
    cvt4(a4_0, hi, lo);
    *(uint2*)&s[OF_AHI + arow*SA + acol] = hi;  *(uint2*)&s[OF_ALO + arow*SA + acol] = lo;
    cvt4(a4_1, hi, lo);
    *(uint2*)&s[OF_AHI + (arow+64)*SA + acol] = hi; *(uint2*)&s[OF_ALO + (arow+64)*SA + acol] = lo;
    cvt4(b4, hi, lo);
    *(uint2*)&s[OF_BHI + arow*SA + acol] = hi;  *(uint2*)&s[OF_BLO + arow*SA + acol] = lo;
  }
  __syncthreads();

  for (int it=0; it<nIter; it++){
    if (it+1<nIter){
      int k0 = (it+1)<<4;
      a4_0 = *(const float4*)(Ap0+k0);
      a4_1 = *(const float4*)(Ap1+k0);
      b4   = bok ? *(const float4*)(Bp+k0) : make_float4(0.f,0.f,0.f,0.f);
    }
    // compute from sm[p]
    {
      const __nv_bfloat16* s = sm[p];
      uint32_t ahi[2][4], alo[2][4], bhi[2][4], blo[2][4];
      ldmx4(smaddr(s + OF_AHI + a_off0), ahi[0]);
      ldmx4(smaddr(s + OF_AHI + a_off1), ahi[1]);
      ldmx4(smaddr(s + OF_ALO + a_off0), alo[0]);
      ldmx4(smaddr(s + OF_ALO + a_off1), alo[1]);
      ldmx4(smaddr(s + OF_BHI + b_off0), bhi[0]);
      ldmx4(smaddr(s + OF_BHI + b_off1), bhi[1]);
      ldmx4(smaddr(s + OF_BLO + b_off0), blo[0]);
      ldmx4(smaddr(s + OF_BLO + b_off1), blo[1]);
      #pragma unroll
      for (int mt=0;mt<2;mt++){
        #pragma unroll
        for (int nt=0;nt<4;nt++){
          int pr = nt>>1, hf = (nt&1)*2;
          mma16816(acc[mt][nt], ahi[mt], bhi[pr][hf], bhi[pr][hf+1]);
          mma16816(acc[mt][nt], ahi[mt], blo[pr][hf], blo[pr][hf+1]);
          mma16816(acc[mt][nt], alo[mt], bhi[pr][hf], bhi[pr][hf+1]);
        }
      }
    }
    __syncthreads();
    if (it+1<nIter){
      uint2 hi,lo;
      __nv_bfloat16* s = sm[p^1];
      cvt4(a4_0, hi, lo);
      *(uint2*)&s[OF_AHI + arow*SA + acol] = hi;  *(uint2*)&s[OF_ALO + arow*SA + acol] = lo;
      cvt4(a4_1, hi, lo);
      *(uint2*)&s[OF_AHI + (arow+64)*SA + acol] = hi; *(uint2*)&s[OF_ALO + (arow+64)*SA + acol] = lo;
      cvt4(b4, hi, lo);
      *(uint2*)&s[OF_BHI + arow*SA + acol] = hi;  *(uint2*)&s[OF_BLO + arow*SA + acol] = lo;
      __syncthreads();
    }
    p ^= 1;
  }

  // epilogue
  #pragma unroll
  for (int mt=0;mt<2;mt++){
    #pragma unroll
    for (int nt=0;nt<4;nt++){
      int r0 = m0 + wm*32 + mt*16 + (lane>>2);
      int cN = n0 + wn*32 + nt*8 + (lane&3)*2;
      float b0 = 0.f, b1 = 0.f;
      if (ACT==0 && bias){ b0 = bias[cN]; b1 = bias[cN+1]; }
      float v0 = acc[mt][nt][0] + b0;
      float v1 = acc[mt][nt][1] + b1;
      float v2 = acc[mt][nt][2] + b0;
      float v3 = acc[mt][nt][3] + b1;
      if (ACT==1){
        v0 = v0/(1.f+expf(-v0)); v1 = v1/(1.f+expf(-v1));
        v2 = v2/(1.f+expf(-v2)); v3 = v3/(1.f+expf(-v3));
      }
      *(float2*)&C[(size_t)r0*ldc + cN]     = make_float2(v0,v1);
      *(float2*)&C[(size_t)(r0+8)*ldc + cN] = make_float2(v2,v3);
    }
  }
}

// ---------------- params elementwise: P -> gate/decay ----------------
__global__ void __launch_bounds__(256) params_elem(const float* __restrict__ temp,
                                                   float* __restrict__ out_gate){
  int idx = blockIdx.x*256 + threadIdx.x;
  if (idx >= ROWS*Hv) return;
  int row = idx/Hv, h = idx - row*Hv;
  const float* sp = g_P + (size_t)row*64 + h*5;
  float p0=sp[0], p1=sp[1], p2=sp[2], p3=sp[3], p4=sp[4];
  const float PI = 3.14159265358979323846f;
  float sa  = 1.f/(1.f+expf(-p0));
  float sph = tanhf(p1)*PI;
  float ca  = 1.f/(1.f+expf(-p2));
  float cph = tanhf(p3)*PI;
  float dec = 0.3f + 0.65f*(1.f/(1.f+expf(-p4)));
  float gate = 1.f/(1.f+expf(-(sa*ca*cosf(sph-cph)*temp[0])));
  int b = row>>10;
  int l = row & (Lv-1);
  int o = (b*Hv+h)*Lv + l;
  g_decay[o]=dec; g_gate[o]=gate;
  if (out_gate) out_gate[idx]=gate;
}

// ---------------- per-(b,h) cumsum(log decay) -> fused scalars ----------------
__global__ void __launch_bounds__(32) scanprep_kernel(){
  int bh = blockIdx.x;
  int lane = threadIdx.x;
  int base = bh*Lv;
  double carry = 0.0;
  for (int l0=0;l0<Lv;l0+=32){
    float dec  = g_decay[base+l0+lane];
    float gate = g_gate [base+l0+lane];
    float s = logf(dec);
    #pragma unroll
    for (int o=1;o<32;o<<=1){
      float nv = __shfl_up_sync(0xffffffffu, s, o);
      if (lane>=o) s += nv;
    }
    float ls = (float)(carry + (double)s);
    float df = expf(ls);
    g_scal[base+l0+lane] = make_float4(df, 1.f/(df+1e-8f), gate*(1.f-dec), 1.f-dec);
    float last = __shfl_sync(0xffffffffu, s, 31);
    carry += (double)last;
  }
}

// ---------------- scan pass 1: per-chunk local state sums ----------------
__global__ void __launch_bounds__(256) scan_partial(){
  int blk = blockIdx.x;
  int bh = blk>>5, c = blk&(CH-1);
  int b = bh/Hv, h = bh - b*Hv;
  int base = b*Lv + c*Tc;
  int t = threadIdx.x, e = t&63, dg = t>>6;
  __shared__ __align__(16) float sk[2][64];
  __shared__ __align__(16) float sv[2][64];
  __shared__ float4 sscal[2];
  float C[16];
  #pragma unroll
  for (int j=0;j<16;j++) C[j]=0.f;
  float zc = 0.f;
  {
    const float* qb = g_qkv + (size_t)base*3*Dv;
    if (t<64)       { float k = qb[Dv+h*64+t];      sk[0][t]    = k>0.f ? k+1.f : expf(k); }
    else if (t<128) { sv[0][t-64] = qb[2*Dv+h*64+(t-64)]; }
    else if (t==128){ sscal[0] = g_scal[bh*Lv + c*Tc]; }
  }
  __syncthreads();
  int p=0;
  for (int i=0;i<Tc;i++){
    if (i+1<Tc){
      const float* qb = g_qkv + (size_t)(base+i+1)*3*Dv;
      int pn=p^1;
      if (t<64)       { float k = qb[Dv+h*64+t];      sk[pn][t]    = k>0.f ? k+1.f : expf(k); }
      else if (t<128) { sv[pn][t-64] = qb[2*Dv+h*64+(t-64)]; }
      else if (t==128){ sscal[pn] = g_scal[bh*Lv + c*Tc + i + 1]; }
    }
    float4 sc = sscal[p];
    float vgo = sv[p][e]*sc.z;
    float inv = sc.y;
    const float4* k4 = (const float4*)&sk[p][dg*16];
    #pragma unroll
    for (int j=0;j<4;j++){
      float4 kf = k4[j];
      float kv;
      kv = fminf(fmaxf(kf.x*vgo,-5.f),5.f); C[4*j+0]=fmaf(kv,inv,C[4*j+0]);
      kv = fminf(fmaxf(kf.y*vgo,-5.f),5.f); C[4*j+1]=fmaf(kv,inv,C[4*j+1]);
      kv = fminf(fmaxf(kf.z*vgo,-5.f),5.f); C[4*j+2]=fmaf(kv,inv,C[4*j+2]);
      kv = fminf(fmaxf(kf.w*vgo,-5.f),5.f); C[4*j+3]=fmaf(kv,inv,C[4*j+3]);
    }
    if (dg==0){
      zc = fmaf(sk[p][e]*sc.w, inv, zc);
    }
    __syncthreads();
    p ^= 1;
  }
  size_t o = (size_t)blk*4096 + (size_t)dg*16*64 + e;
  #pragma unroll
  for (int j=0;j<16;j++) g_csum[o + j*64] = C[j];
  if (dg==0) g_zsum[blk*64+e] = zc;
}

// ---------------- scan pass 1.5: exclusive chunk prefixes per bh ----------------
__global__ void __launch_bounds__(256) scan_combine(){
  int bh = blockIdx.x;
  int t = threadIdx.x, e = t&63, dg = t>>6;
  float acc[16];
  #pragma unroll
  for (int j=0;j<16;j++) acc[j]=0.f;
  float zacc = 0.f;
  for (int c=0;c<CH;c++){
    int blk = bh*CH + c;
    size_t o = (size_t)blk*4096 + (size_t)dg*16*64 + e;
    #pragma unroll
    for (int j=0;j<16;j++){
      float s = g_csum[o + j*64];
      g_carry[o + j*64] = acc[j];
      acc[j] += s;
    }
    if (dg==0){
      g_zcarry[blk*64+e] = zacc;
      zacc += g_zsum[blk*64+e];
    }
  }
}

// ---------------- scan pass 2: carry-initialized sequential scan + outputs ----------------
__global__ void __launch_bounds__(256) scan_main(){
  int blk = blockIdx.x;
  int bh = blk>>5, c = blk&(CH-1);
  int b = bh/Hv, h = bh - b*Hv;
  int base = b*Lv + c*Tc;
  int t = threadIdx.x, e = t&63, dg = t>>6;
  __shared__ __align__(16) float sq[2][64];
  __shared__ __align__(16) float sk[2][64];
  __shared__ __align__(16) float sv[2][64];
  __shared__ float4 sscal[2];
  float C[16];
  {
    size_t o = (size_t)blk*4096 + (size_t)dg*16*64 + e;
    #pragma unroll
    for (int j=0;j<16;j++) C[j] = g_carry[o + j*64];
  }
  float zc = g_zcarry[blk*64+e];
  {
    const float* qb = g_qkv + (size_t)base*3*Dv;
    if (t<64)       { float q = qb[h*64+t];          sq[0][t]    = q>0.f ? q+1.f : expf(q); }
    else if (t<128) { int d=t-64;  float k = qb[Dv+h*64+d];  sk[0][d] = k>0.f ? k+1.f : expf(k); }
    else if (t<192) { int d=t-128; sv[0][d] = qb[2*Dv+h*64+d]; }
    else if (t==192){ sscal[0] = g_scal[bh*Lv + c*Tc]; }
  }
  __syncthreads();
  int p=0;
  for (int i=0;i<Tc;i++){
    if (i+1<Tc){
      const float* qb = g_qkv + (size_t)(base+i+1)*3*Dv;
      int pn=p^1;
      if (t<64)       { float q = qb[h*64+t];          sq[pn][t]    = q>0.f ? q+1.f : expf(q); }
      else if (t<128) { int d=t-64;  float k = qb[Dv+h*64+d];  sk[pn][d] = k>0.f ? k+1.f : expf(k); }
      else if (t<192) { int d=t-128; sv[pn][d] = qb[2*Dv+h*64+d]; }
      else if (t==192){ sscal[pn] = g_scal[bh*Lv + c*Tc + i + 1]; }
    }
    float4 sc = sscal[p];
    float vgo = sv[p][e]*sc.z;
    float inv = sc.y, df = sc.x;
    const float4* k4 = (const float4*)&sk[p][dg*16];
    const float4* q4 = (const float4*)&sq[p][dg*16];
    float a0=0.f,a1=0.f,a2=0.f,a3=0.f;
    #pragma unroll
    for (int j=0;j<4;j++){
      float4 kf = k4[j], qf = q4[j];
      float kv;
      kv = fminf(fmaxf(kf.x*vgo,-5.f),5.f); C[4*j+0]=fmaf(kv,inv,C[4*j+0]); a0=fmaf(qf.x,C[4*j+0],a0);
      kv = fminf(fmaxf(kf.y*vgo,-5.f),5.f); C[4*j+1]=fmaf(kv,inv,C[4*j+1]); a1=fmaf(qf.y,C[4*j+1],a1);
      kv = fminf(fmaxf(kf.z*vgo,-5.f),5.f); C[4*j+2]=fmaf(kv,inv,C[4*j+2]); a2=fmaf(qf.z,C[4*j+2],a2);
      kv = fminf(fmaxf(kf.w*vgo,-5.f),5.f); C[4*j+3]=fmaf(kv,inv,C[4*j+3]); a3=fmaf(qf.w,C[4*j+3],a3);
    }
    float acc = (a0+a1)+(a2+a3);
    int row = base + i;
    g_pacc[(((size_t)row*Hv + h)*4 + dg)*64 + e] = acc*df;
    if (dg==0){
      zc = fmaf(sk[p][e]*sc.w, inv, zc);
      float z = zc*df;
      z = fminf(fmaxf(z,-10000.f),10000.f);
      g_qz[((size_t)row*Hv + h)*64 + e] = sq[p][e]*z;
    }
    __syncthreads();
    p ^= 1;
  }
}

// ---------------- finalize: den reduce + mini layernorm over e ----------------
__global__ void __launch_bounds__(64) finalize_kernel(const float* __restrict__ mg,
                                                      const float* __restrict__ mb){
  int id = blockIdx.x;
  int e = threadIdx.x;
  __shared__ float s2[2];
  size_t base = (size_t)id*4*64;
  float num = g_pacc[base+e] + g_pacc[base+64+e] + g_pacc[base+128+e] + g_pacc[base+192+e];
  float qz  = g_qz[(size_t)id*64+e];
  float den = sum64(qz, s2) + 1e-4f;
  float val = num/den;
  float mu  = sum64(val, s2) * (1.f/64.f);
  float dlt = val - mu;
  float var = sum64(dlt*dlt, s2) * (1.f/64.f);
  float res = dlt/sqrtf(var+1e-5f)*mg[e] + mb[e];
  int row = id/Hv, h = id - row*Hv;
  g_attn[(size_t)row*Dv + h*64 + e] = res;
}

// ---------------- launch ----------------
extern "C" void kernel_launch(void* const* d_in, const int* in_sizes, int n_in,
                              void* d_out, int out_size){
  const float* x      = (const float*)d_in[0];
  const float* conv_w = (const float*)d_in[1];
  const float* conv_b = (const float*)d_in[2];
  const float* ln_g   = (const float*)d_in[3];
  const float* ln_b   = (const float*)d_in[4];
  const float* qkv_w  = (const float*)d_in[5];
  const float* qkv_b  = (const float*)d_in[6];
  const float* bn_w1  = (const float*)d_in[7];
  const float* bn_w2  = (const float*)d_in[8];
  const float* temp   = (const float*)d_in[9];
  const float* proj_w = (const float*)d_in[10];
  const float* proj_b = (const float*)d_in[11];
  const float* mn_g   = (const float*)d_in[12];
  const float* mn_b   = (const float*)d_in[13];
  float* out = (float*)d_out;
  float* gate_out = ((size_t)out_size >= (size_t)ROWS*Dv + (size_t)ROWS*Hv)
                    ? out + (size_t)ROWS*Dv : nullptr;

  void *p_xn, *p_qkv, *p_h1, *p_P, *p_attn;
  cudaGetSymbolAddress(&p_xn,  g_xn);
  cudaGetSymbolAddress(&p_qkv, g_qkv);
  cudaGetSymbolAddress(&p_h1,  g_h1);
  cudaGetSymbolAddress(&p_P,   g_P);
  cudaGetSymbolAddress(&p_attn,g_attn);

  conv_ln_kernel<<<ROWS,256>>>(x, conv_w, conv_b, ln_g, ln_b);
  // QKV: 2048 x 2304 x 768
  gemm_tc<0><<<dim3((3*Dv)/64, ROWS/128),256>>>((const float*)p_xn, qkv_w, qkv_b,
                                                (float*)p_qkv, Dv, 3*Dv, 3*Dv);
  // bn1 = silu(xn @ bn_w1^T): 2048 x 256 x 768
  gemm_tc<1><<<dim3(Rv/64, ROWS/128),256>>>((const float*)p_xn, bn_w1, nullptr,
                                            (float*)p_h1, Dv, Rv, Rv);
  // params P = h1 @ bn_w2^T: 2048 x 60 x 256 (ldc=64, B rows valid: 60)
  gemm_tc<0><<<dim3(1, ROWS/128),256>>>((const float*)p_h1, bn_w2, nullptr,
                                        (float*)p_P, Rv, 64, Hv*5);
  params_elem<<<(ROWS*Hv+255)/256,256>>>(temp, gate_out);
  scanprep_kernel<<<BHn,32>>>();
  scan_partial<<<BHn*CH,256>>>();
  scan_combine<<<BHn,256>>>();
  scan_main<<<BHn*CH,256>>>();
  finalize_kernel<<<ROWS*Hv,64>>>(mn_g, mn_b);
  // proj: 2048 x 768 x 768
  gemm_tc<0><<<dim3(Dv/64, ROWS/128),256>>>((const float*)p_attn, proj_w, proj_b,
                                            out, Dv, Dv, Dv);
}

// round 14
// speedup vs baseline: 3.0751x; 1.0117x over previous
#include <cuda_runtime.h>
#include <cuda_bf16.h>
#include <math.h>
#include <stdint.h>
#include <stddef.h>

#define Bv 2
#define Lv 1024
#define Dv 768
#define Hv 12
#define DHv 64
#define Rv 256
#define ROWS (Bv*Lv)   // 2048
#define BHn (Bv*Hv)    // 24
#define CH 32          // scan chunks
#define Tc 32          // steps per chunk

// ---------------- scratch (device globals: allocation-free) ----------------
__device__ float g_xn[ROWS*Dv];
__device__ float g_qkv[(size_t)ROWS*3*Dv];
__device__ float g_h1[ROWS*Rv];
__device__ float g_P[ROWS*64];
__device__ float4 g_scal[BHn*Lv];                  // df, 1/(df+1e-8), gate*(1-dec), (1-dec)
__device__ float g_csum[(size_t)BHn*CH*DHv*DHv];
__device__ float g_carry[(size_t)BHn*CH*DHv*DHv];
__device__ float g_zsum[BHn*CH*DHv];
__device__ float g_zcarry[BHn*CH*DHv];
__device__ float g_attn[ROWS*Dv];

// ---------------- reductions ----------------
__device__ __forceinline__ float block_sum_256(float v, float* s8){
  #pragma unroll
  for (int o=16;o>0;o>>=1) v += __shfl_xor_sync(0xffffffffu, v, o);
  if ((threadIdx.x&31)==0) s8[threadIdx.x>>5]=v;
  __syncthreads();
  float r = s8[0];
  #pragma unroll
  for (int i=1;i<8;i++) r += s8[i];
  __syncthreads();
  return r;
}

// 64-thread-group sum; MUST be called by all 256 threads (uniform syncs).
__device__ __forceinline__ float grp64_sum(float v, int dg, float* sred){
  #pragma unroll
  for (int o=16;o>0;o>>=1) v += __shfl_xor_sync(0xffffffffu, v, o);
  int half = (threadIdx.x>>5)&1;
  if ((threadIdx.x&31)==0) sred[dg*2+half] = v;
  __syncthreads();
  float r = sred[dg*2] + sred[dg*2+1];
  __syncthreads();
  return r;
}

// ---------------- K1: causal depthwise conv(3) + residual + LayerNorm ----------------
__global__ void __launch_bounds__(256) conv_ln_kernel(const float* __restrict__ x,
    const float* __restrict__ cw, const float* __restrict__ cb,
    const float* __restrict__ lg, const float* __restrict__ lb){
  int row = blockIdx.x;
  int l = row & (Lv-1);
  __shared__ float sxc[Dv];
  __shared__ float s8[8];
  int t = threadIdx.x;
  float sum = 0.f;
  #pragma unroll
  for (int i=0;i<3;i++){
    int d = t + i*256;
    float x0  = x[(size_t)row*Dv + d];
    float xm1 = (l>=1) ? x[(size_t)(row-1)*Dv + d] : 0.f;
    float xm2 = (l>=2) ? x[(size_t)(row-2)*Dv + d] : 0.f;
    float c = xm2*cw[d*3+0] + xm1*cw[d*3+1] + x0*cw[d*3+2] + cb[d];
    float xc = x0 + c;
    sxc[d] = xc;
    sum += xc;
  }
  float mu = block_sum_256(sum, s8) * (1.f/(float)Dv);
  float sq = 0.f;
  #pragma unroll
  for (int i=0;i<3;i++){ float dlt = sxc[t+i*256]-mu; sq += dlt*dlt; }
  float var = block_sum_256(sq, s8) * (1.f/(float)Dv);
  float inv = 1.f/sqrtf(var + 1e-5f);
  #pragma unroll
  for (int i=0;i<3;i++){
    int d = t+i*256;
    g_xn[(size_t)row*Dv+d] = (sxc[d]-mu)*inv*lg[d] + lb[d];
  }
}

// ================= tensor-core GEMM (bf16 3-term split, fp32 acc) =================
__device__ __forceinline__ uint32_t smaddr(const void* p){
  return (uint32_t)__cvta_generic_to_shared(p);
}
__device__ __forceinline__ uint32_t packbf(__nv_bfloat16 a, __nv_bfloat16 b){
  return (uint32_t)__bfloat16_as_ushort(a) | ((uint32_t)__bfloat16_as_ushort(b)<<16);
}
__device__ __forceinline__ void cvt4(float4 v, uint2& hi, uint2& lo){
  __nv_bfloat16 hx=__float2bfloat16_rn(v.x), hy=__float2bfloat16_rn(v.y);
  __nv_bfloat16 hz=__float2bfloat16_rn(v.z), hw=__float2bfloat16_rn(v.w);
  __nv_bfloat16 lx=__float2bfloat16_rn(v.x-__bfloat162float(hx));
  __nv_bfloat16 ly=__float2bfloat16_rn(v.y-__bfloat162float(hy));
  __nv_bfloat16 lz=__float2bfloat16_rn(v.z-__bfloat162float(hz));
  __nv_bfloat16 lw=__float2bfloat16_rn(v.w-__bfloat162float(hw));
  hi.x = packbf(hx,hy); hi.y = packbf(hz,hw);
  lo.x = packbf(lx,ly); lo.y = packbf(lz,lw);
}
__device__ __forceinline__ void ldmx4(uint32_t a, uint32_t* r){
  asm volatile("ldmatrix.sync.aligned.m8n8.x4.shared.b16 {%0,%1,%2,%3}, [%4];"
    : "=r"(r[0]),"=r"(r[1]),"=r"(r[2]),"=r"(r[3]) : "r"(a));
}
__device__ __forceinline__ void mma16816(float* c, const uint32_t* a, uint32_t b0, uint32_t b1){
  asm volatile("mma.sync.aligned.m16n8k16.row.col.f32.bf16.bf16.f32 "
    "{%0,%1,%2,%3}, {%4,%5,%6,%7}, {%8,%9}, {%0,%1,%2,%3};"
    : "+f"(c[0]),"+f"(c[1]),"+f"(c[2]),"+f"(c[3])
    : "r"(a[0]),"r"(a[1]),"r"(a[2]),"r"(a[3]), "r"(b0),"r"(b1));
}

#define SA 24                    // smem row stride in bf16 (48B: conflict-free ldmatrix)
#define OF_AHI 0
#define OF_ALO 3072
#define OF_BHI 6144
#define OF_BLO 7680
#define STG 9216

template<int ACT>
__global__ void __launch_bounds__(256) gemm_tc(const float* __restrict__ A,
    const float* __restrict__ Bm, const float* __restrict__ bias,
    float* __restrict__ C, int K, int ldc, int Nb){
  __shared__ __align__(16) __nv_bfloat16 sm[2][STG];
  int t = threadIdx.x;
  int m0 = blockIdx.y*128, n0 = blockIdx.x*64;
  int lane = t&31, wid = t>>5;
  int wm = wid&3, wn = wid>>2;

  int arow = t>>2, acol = (t&3)*4;
  const float* Ap0 = A + (size_t)(m0+arow)*K + acol;
  const float* Ap1 = A + (size_t)(m0+arow+64)*K + acol;
  bool bok = (n0+arow) < Nb;
  const float* Bp = Bm + (size_t)(n0+arow)*K + acol;

  float acc[2][4][4];
  #pragma unroll
  for (int i=0;i<2;i++)
    #pragma unroll
    for (int j=0;j<4;j++)
      #pragma unroll
      for (int q=0;q<4;q++) acc[i][j][q]=0.f;

  float4 a4_0 = *(const float4*)(Ap0);
  float4 a4_1 = *(const float4*)(Ap1);
  float4 b4   = bok ? *(const float4*)(Bp) : make_float4(0.f,0.f,0.f,0.f);

  int a_off0 = (wm*32 + (lane&15))*SA + (lane>>4)*8;
  int a_off1 = a_off0 + 16*SA;
  int b_r    = wn*32 + (lane&7) + ((lane>>4)<<3);
  int b_c    = ((lane>>3)&1)*8;
  int b_off0 = b_r*SA + b_c;
  int b_off1 = (b_r+16)*SA + b_c;

  int nIter = K>>4;
  int p = 0;
  {
    uint2 hi,lo;
    __nv_bfloat16* s = sm[0];
    cvt4(a4_0, hi, lo);
    *(uint2*)&s[OF_AHI + arow*SA + acol] = hi;  *(uint2*)&s[OF_ALO + arow*SA + acol] = lo;
    cvt4(a4_1, hi, lo);
    *(uint2*)&s[OF_AHI + (arow+64)*SA + acol] = hi; *(uint2*)&s[OF_ALO + (arow+64)*SA + acol] = lo;
    cvt4(b4, hi, lo);
    *(uint2*)&s[OF_BHI + arow*SA + acol] = hi;  *(uint2*)&s[OF_BLO + arow*SA + acol] = lo;
  }
  __syncthreads();

  for (int it=0; it<nIter; it++){
    if (it+1<nIter){
      int k0 = (it+1)<<4;
      a4_0 = *(const float4*)(Ap0+k0);
      a4_1 = *(const float4*)(Ap1+k0);
      b4   = bok ? *(const float4*)(Bp+k0) : make_float4(0.f,0.f,0.f,0.f);
    }
    {
      const __nv_bfloat16* s = sm[p];
      uint32_t ahi[2][4], alo[2][4], bhi[2][4], blo[2][4];
      ldmx4(smaddr(s + OF_AHI + a_off0), ahi[0]);
      ldmx4(smaddr(s + OF_AHI + a_off1), ahi[1]);
      ldmx4(smaddr(s + OF_ALO + a_off0), alo[0]);
      ldmx4(smaddr(s + OF_ALO + a_off1), alo[1]);
      ldmx4(smaddr(s + OF_BHI + b_off0), bhi[0]);
      ldmx4(smaddr(s + OF_BHI + b_off1), bhi[1]);
      ldmx4(smaddr(s + OF_BLO + b_off0), blo[0]);
      ldmx4(smaddr(s + OF_BLO + b_off1), blo[1]);
      #pragma unroll
      for (int mt=0;mt<2;mt++){
        #pragma unroll
        for (int nt=0;nt<4;nt++){
          int pr = nt>>1, hf = (nt&1)*2;
          mma16816(acc[mt][nt], ahi[mt], bhi[pr][hf], bhi[pr][hf+1]);
          mma16816(acc[mt][nt], ahi[mt], blo[pr][hf], blo[pr][hf+1]);
          mma16816(acc[mt][nt], alo[mt], bhi[pr][hf], bhi[pr][hf+1]);
        }
      }
    }
    __syncthreads();
    if (it+1<nIter){
      uint2 hi,lo;
      __nv_bfloat16* s = sm[p^1];
      cvt4(a4_0, hi, lo);
      *(uint2*)&s[OF_AHI + arow*SA + acol] = hi;  *(uint2*)&s[OF_ALO + arow*SA + acol] = lo;
      cvt4(a4_1, hi, lo);
      *(uint2*)&s[OF_AHI + (arow+64)*SA + acol] = hi; *(uint2*)&s[OF_ALO + (arow+64)*SA + acol] = lo;
      cvt4(b4, hi, lo);
      *(uint2*)&s[OF_BHI + arow*SA + acol] = hi;  *(uint2*)&s[OF_BLO + arow*SA + acol] = lo;
      __syncthreads();
    }
    p ^= 1;
  }

  #pragma unroll
  for (int mt=0;mt<2;mt++){
    #pragma unroll
    for (int nt=0;nt<4;nt++){
      int r0 = m0 + wm*32 + mt*16 + (lane>>2);
      int cN = n0 + wn*32 + nt*8 + (lane&3)*2;
      float b0 = 0.f, b1 = 0.f;
      if (ACT==0 && bias){ b0 = bias[cN]; b1 = bias[cN+1]; }
      float v0 = acc[mt][nt][0] + b0;
      float v1 = acc[mt][nt][1] + b1;
      float v2 = acc[mt][nt][2] + b0;
      float v3 = acc[mt][nt][3] + b1;
      if (ACT==1){
        v0 = v0/(1.f+expf(-v0)); v1 = v1/(1.f+expf(-v1));
        v2 = v2/(1.f+expf(-v2)); v3 = v3/(1.f+expf(-v3));
      }
      *(float2*)&C[(size_t)r0*ldc + cN]     = make_float2(v0,v1);
      *(float2*)&C[(size_t)(r0+8)*ldc + cN] = make_float2(v2,v3);
    }
  }
}

// ---------------- fused params + per-(b,h) log-decay scan ----------------
// block per bh, 32 lanes. Reads g_P, emits gate output + g_scal directly.
__global__ void __launch_bounds__(32) params_scan_kernel(const float* __restrict__ temp,
                                                         float* __restrict__ out_gate){
  int bh = blockIdx.x;
  int b = bh/Hv, h = bh - b*Hv;
  int lane = threadIdx.x;
  float T = temp[0];
  const float PI = 3.14159265358979323846f;
  double carry = 0.0;
  for (int l0=0;l0<Lv;l0+=32){
    int l = l0 + lane;
    int row = b*Lv + l;
    const float* sp = g_P + (size_t)row*64 + h*5;
    float p0=sp[0], p1=sp[1], p2=sp[2], p3=sp[3], p4=sp[4];
    float sa  = 1.f/(1.f+expf(-p0));
    float sph = tanhf(p1)*PI;
    float ca  = 1.f/(1.f+expf(-p2));
    float cph = tanhf(p3)*PI;
    float dec = 0.3f + 0.65f*(1.f/(1.f+expf(-p4)));
    float gate = 1.f/(1.f+expf(-(sa*ca*cosf(sph-cph)*T)));
    if (out_gate) out_gate[(size_t)row*Hv + h] = gate;
    float s = logf(dec);
    #pragma unroll
    for (int o=1;o<32;o<<=1){
      float nv = __shfl_up_sync(0xffffffffu, s, o);
      if (lane>=o) s += nv;
    }
    float ls = (float)(carry + (double)s);
    float df = expf(ls);
    g_scal[bh*Lv + l] = make_float4(df, 1.f/(df+1e-8f), gate*(1.f-dec), 1.f-dec);
    float last = __shfl_sync(0xffffffffu, s, 31);
    carry += (double)last;
  }
}

// ---------------- scan pass 1: per-chunk local state sums ----------------
__global__ void __launch_bounds__(256) scan_partial(){
  int blk = blockIdx.x;
  int bh = blk>>5, c = blk&(CH-1);
  int b = bh/Hv, h = bh - b*Hv;
  int base = b*Lv + c*Tc;
  int t = threadIdx.x, e = t&63, dg = t>>6;
  __shared__ __align__(16) float sk[2][64];
  __shared__ __align__(16) float sv[2][64];
  __shared__ float4 sscal[2];
  float C[16];
  #pragma unroll
  for (int j=0;j<16;j++) C[j]=0.f;
  float zc = 0.f;
  {
    const float* qb = g_qkv + (size_t)base*3*Dv;
    if (t<64)       { float k = qb[Dv+h*64+t];      sk[0][t]    = k>0.f ? k+1.f : expf(k); }
    else if (t<128) { sv[0][t-64] = qb[2*Dv+h*64+(t-64)]; }
    else if (t==128){ sscal[0] = g_scal[bh*Lv + c*Tc]; }
  }
  __syncthreads();
  int p=0;
  for (int i=0;i<Tc;i++){
    if (i+1<Tc){
      const float* qb = g_qkv + (size_t)(base+i+1)*3*Dv;
      int pn=p^1;
      if (t<64)       { float k = qb[Dv+h*64+t];      sk[pn][t]    = k>0.f ? k+1.f : expf(k); }
      else if (t<128) { sv[pn][t-64] = qb[2*Dv+h*64+(t-64)]; }
      else if (t==128){ sscal[pn] = g_scal[bh*Lv + c*Tc + i + 1]; }
    }
    float4 sc = sscal[p];
    float vgo = sv[p][e]*sc.z;
    float inv = sc.y;
    const float4* k4 = (const float4*)&sk[p][dg*16];
    #pragma unroll
    for (int j=0;j<4;j++){
      float4 kf = k4[j];
      float kv;
      kv = fminf(fmaxf(kf.x*vgo,-5.f),5.f); C[4*j+0]=fmaf(kv,inv,C[4*j+0]);
      kv = fminf(fmaxf(kf.y*vgo,-5.f),5.f); C[4*j+1]=fmaf(kv,inv,C[4*j+1]);
      kv = fminf(fmaxf(kf.z*vgo,-5.f),5.f); C[4*j+2]=fmaf(kv,inv,C[4*j+2]);
      kv = fminf(fmaxf(kf.w*vgo,-5.f),5.f); C[4*j+3]=fmaf(kv,inv,C[4*j+3]);
    }
    if (dg==0){
      zc = fmaf(sk[p][e]*sc.w, inv, zc);
    }
    __syncthreads();
    p ^= 1;
  }
  size_t o = (size_t)blk*4096 + (size_t)dg*16*64 + e;
  #pragma unroll
  for (int j=0;j<16;j++) g_csum[o + j*64] = C[j];
  if (dg==0) g_zsum[blk*64+e] = zc;
}

// ---------------- scan pass 1.5: exclusive chunk prefixes per bh ----------------
__global__ void __launch_bounds__(256) scan_combine(){
  int bh = blockIdx.x;
  int t = threadIdx.x, e = t&63, dg = t>>6;
  float acc[16];
  #pragma unroll
  for (int j=0;j<16;j++) acc[j]=0.f;
  float zacc = 0.f;
  for (int c=0;c<CH;c++){
    int blk = bh*CH + c;
    size_t o = (size_t)blk*4096 + (size_t)dg*16*64 + e;
    #pragma unroll
    for (int j=0;j<16;j++){
      float s = g_csum[o + j*64];
      g_carry[o + j*64] = acc[j];
      acc[j] += s;
    }
    if (dg==0){
      g_zcarry[blk*64+e] = zacc;
      zacc += g_zsum[blk*64+e];
    }
  }
}

// ---------------- scan pass 2: carry-init scan + FUSED den/mini-LN finalize ----------------
__global__ void __launch_bounds__(256) scan_main(const float* __restrict__ mg,
                                                 const float* __restrict__ mb){
  int blk = blockIdx.x;
  int bh = blk>>5, c = blk&(CH-1);
  int b = bh/Hv, h = bh - b*Hv;
  int base = b*Lv + c*Tc;
  int t = threadIdx.x, e = t&63, dg = t>>6;
  __shared__ __align__(16) float sq[2][64];
  __shared__ __align__(16) float sk[2][64];
  __shared__ __align__(16) float sv[2][64];
  __shared__ float4 sscal[2];
  __shared__ float spart[Tc][4][64];   // per-step per-dg partial out_num (x df)
  __shared__ float sqz[Tc][64];        // per-step q*z
  __shared__ float sred[8];
  float C[16];
  {
    size_t o = (size_t)blk*4096 + (size_t)dg*16*64 + e;
    #pragma unroll
    for (int j=0;j<16;j++) C[j] = g_carry[o + j*64];
  }
  float zc = g_zcarry[blk*64+e];
  {
    const float* qb = g_qkv + (size_t)base*3*Dv;
    if (t<64)       { float q = qb[h*64+t];          sq[0][t]    = q>0.f ? q+1.f : expf(q); }
    else if (t<128) { int d=t-64;  float k = qb[Dv+h*64+d];  sk[0][d] = k>0.f ? k+1.f : expf(k); }
    else if (t<192) { int d=t-128; sv[0][d] = qb[2*Dv+h*64+d]; }
    else if (t==192){ sscal[0] = g_scal[bh*Lv + c*Tc]; }
  }
  __syncthreads();
  int p=0;
  for (int i=0;i<Tc;i++){
    if (i+1<Tc){
      const float* qb = g_qkv + (size_t)(base+i+1)*3*Dv;
      int pn=p^1;
      if (t<64)       { float q = qb[h*64+t];          sq[pn][t]    = q>0.f ? q+1.f : expf(q); }
      else if (t<128) { int d=t-64;  float k = qb[Dv+h*64+d];  sk[pn][d] = k>0.f ? k+1.f : expf(k); }
      else if (t<192) { int d=t-128; sv[pn][d] = qb[2*Dv+h*64+d]; }
      else if (t==192){ sscal[pn] = g_scal[bh*Lv + c*Tc + i + 1]; }
    }
    float4 sc = sscal[p];
    float vgo = sv[p][e]*sc.z;
    float inv = sc.y, df = sc.x;
    const float4* k4 = (const float4*)&sk[p][dg*16];
    const float4* q4 = (const float4*)&sq[p][dg*16];
    float a0=0.f,a1=0.f,a2=0.f,a3=0.f;
    #pragma unroll
    for (int j=0;j<4;j++){
      float4 kf = k4[j], qf = q4[j];
      float kv;
      kv = fminf(fmaxf(kf.x*vgo,-5.f),5.f); C[4*j+0]=fmaf(kv,inv,C[4*j+0]); a0=fmaf(qf.x,C[4*j+0],a0);
      kv = fminf(fmaxf(kf.y*vgo,-5.f),5.f); C[4*j+1]=fmaf(kv,inv,C[4*j+1]); a1=fmaf(qf.y,C[4*j+1],a1);
      kv = fminf(fmaxf(kf.z*vgo,-5.f),5.f); C[4*j+2]=fmaf(kv,inv,C[4*j+2]); a2=fmaf(qf.z,C[4*j+2],a2);
      kv = fminf(fmaxf(kf.w*vgo,-5.f),5.f); C[4*j+3]=fmaf(kv,inv,C[4*j+3]); a3=fmaf(qf.w,C[4*j+3],a3);
    }
    spart[i][dg][e] = ((a0+a1)+(a2+a3))*df;
    if (dg==0){
      zc = fmaf(sk[p][e]*sc.w, inv, zc);
      float z = zc*df;
      z = fminf(fmaxf(z,-10000.f),10000.f);
      sqz[i][e] = sq[p][e]*z;
    }
    __syncthreads();
    p ^= 1;
  }

  // ---- fused finalize: each dg group handles 8 steps ----
  float gv = mg[e], bvv = mb[e];
  #pragma unroll
  for (int j=0;j<8;j++){
    int s = dg*8 + j;
    float num = spart[s][0][e] + spart[s][1][e] + spart[s][2][e] + spart[s][3][e];
    float qz  = sqz[s][e];
    float den = grp64_sum(qz, dg, sred) + 1e-4f;
    float val = num/den;
    float mu  = grp64_sum(val, dg, sred) * (1.f/64.f);
    float dlt = val - mu;
    float var = grp64_sum(dlt*dlt, dg, sred) * (1.f/64.f);
    float res = dlt/sqrtf(var+1e-5f)*gv + bvv;
    int row = base + s;
    g_attn[(size_t)row*Dv + h*64 + e] = res;
  }
}

// ---------------- launch ----------------
extern "C" void kernel_launch(void* const* d_in, const int* in_sizes, int n_in,
                              void* d_out, int out_size){
  const float* x      = (const float*)d_in[0];
  const float* conv_w = (const float*)d_in[1];
  const float* conv_b = (const float*)d_in[2];
  const float* ln_g   = (const float*)d_in[3];
  const float* ln_b   = (const float*)d_in[4];
  const float* qkv_w  = (const float*)d_in[5];
  const float* qkv_b  = (const float*)d_in[6];
  const float* bn_w1  = (const float*)d_in[7];
  const float* bn_w2  = (const float*)d_in[8];
  const float* temp   = (const float*)d_in[9];
  const float* proj_w = (const float*)d_in[10];
  const float* proj_b = (const float*)d_in[11];
  const float* mn_g   = (const float*)d_in[12];
  const float* mn_b   = (const float*)d_in[13];
  float* out = (float*)d_out;
  float* gate_out = ((size_t)out_size >= (size_t)ROWS*Dv + (size_t)ROWS*Hv)
                    ? out + (size_t)ROWS*Dv : nullptr;

  void *p_xn, *p_qkv, *p_h1, *p_P, *p_attn;
  cudaGetSymbolAddress(&p_xn,  g_xn);
  cudaGetSymbolAddress(&p_qkv, g_qkv);
  cudaGetSymbolAddress(&p_h1,  g_h1);
  cudaGetSymbolAddress(&p_P,   g_P);
  cudaGetSymbolAddress(&p_attn,g_attn);

  conv_ln_kernel<<<ROWS,256>>>(x, conv_w, conv_b, ln_g, ln_b);
  // QKV: 2048 x 2304 x 768
  gemm_tc<0><<<dim3((3*Dv)/64, ROWS/128),256>>>((const float*)p_xn, qkv_w, qkv_b,
                                                (float*)p_qkv, Dv, 3*Dv, 3*Dv);
  // bn1 = silu(xn @ bn_w1^T): 2048 x 256 x 768
  gemm_tc<1><<<dim3(Rv/64, ROWS/128),256>>>((const float*)p_xn, bn_w1, nullptr,
                                            (float*)p_h1, Dv, Rv, Rv);
  // params P = h1 @ bn_w2^T: 2048 x 60 x 256 (ldc=64, B rows valid: 60)
  gemm_tc<0><<<dim3(1, ROWS/128),256>>>((const float*)p_h1, bn_w2, nullptr,
                                        (float*)p_P, Rv, 64, Hv*5);
  params_scan_kernel<<<BHn,32>>>(temp, gate_out);
  scan_partial<<<BHn*CH,256>>>();
  scan_combine<<<BHn,256>>>();
  scan_main<<<BHn*CH,256>>>(mn_g, mn_b);
  // proj: 2048 x 768 x 768
  gemm_tc<0><<<dim3(Dv/64, ROWS/128),256>>>((const float*)p_attn, proj_w, proj_b,
                                            out, Dv, Dv, Dv);
}